// round 15
// baseline (speedup 1.0000x reference)
#include <cuda_runtime.h>
#include <cuda_bf16.h>
#include <cstdint>

// Problem constants
#define NUM_CHIPS 4
#define SEQ 1024
#define HIDDEN 2048
#define TOP_K 4
#define N_EXPERTS 32
#define MAX_TOK 1024
#define META_LEN 8
#define N_PER_CHIP (SEQ * TOP_K)           // 4096
#define N_TOTAL (NUM_CHIPS * N_PER_CHIP)   // 16384 assignments
#define N_CHUNKS (N_TOTAL / 32)            // 512 warp-chunks, chip-major
#define TOTAL_SLOTS (N_EXPERTS * MAX_TOK)  // 32768
#define BUF_ELEMS ((size_t)TOTAL_SLOTS * HIDDEN)
#define META_OFF  BUF_ELEMS
#define CNT_OFF   (BUF_ELEMS + (size_t)TOTAL_SLOTS * META_LEN)

#define PLANNERS 64            // planner blocks (all wave-1 co-resident)
#define THREADS 256
#define TICK_ADDRS 1024

// Scratch (no allocations allowed). ALL counters are MONOTONE across graph
// replays: g_pbar +128/replay, g_done +64/replay, each g_tick row +32/replay.
__device__ int g_src[TOTAL_SLOTS];            // slot -> assignment id
__device__ int g_cnt[N_EXPERTS];              // per-expert totals
__device__ int g_wcount[N_EXPERTS][N_CHUNKS]; // chunk counts -> (in place) offsets
__device__ unsigned g_pbar;                   // planner barrier tickets
__device__ unsigned g_done;                   // planner completions
__device__ int g_tick[TICK_ADDRS][32];        // slot-block tickets, 128B-strided rows

// Monotone-window barrier among the PLANNERS blocks. Poll via plain volatile
// loads (no RMW storm).
__device__ __forceinline__ void pbar() {
    __syncthreads();
    __threadfence();
    if (threadIdx.x == 0) {
        const unsigned t = atomicAdd(&g_pbar, 1u);
        const unsigned tgt = (t / PLANNERS + 1u) * PLANNERS;
        while (*(volatile unsigned*)&g_pbar < tgt) { }
    }
    __syncthreads();
    __threadfence();
}

__global__ void __launch_bounds__(THREADS) dispatch_kernel(
    const float* __restrict__ x, const float* __restrict__ w,
    const int* __restrict__ idx, float* __restrict__ out)
{
    const int b = blockIdx.x;

    // ---------------- Planner blocks (bid 0..63) ---------------------------
    if (b < PLANNERS) {
        const int warp = threadIdx.x >> 5;            // 0..7
        const int lane = threadIdx.x & 31;
        const unsigned lt = (1u << lane) - 1u;
        const int chunk = b * 8 + warp;               // 0..511, chip-major
        const int a = chunk * 32 + lane;              // assignment id

        // Phase 1: stable rank within chunk + per-chunk expert counts.
        const int e = __ldg(&idx[a]);
        const unsigned m = __match_any_sync(0xFFFFFFFFu, e);
        const int rk = __popc(m & lt);
        g_wcount[lane][chunk] = 0;                    // zero this chunk's column
        __syncwarp();
        if (rk == 0) g_wcount[e][chunk] = __popc(m);  // group leader

        pbar();

        // Phase 2: block 0 scans each expert's 512 chunk counts in place.
        // 8 warps x 4 experts; lane owns 16 contiguous chunks (two-level scan).
        if (b == 0) {
#pragma unroll
            for (int k = 0; k < 4; k++) {
                const int ex = warp * 4 + k;
                const int4* wc = reinterpret_cast<const int4*>(&g_wcount[ex][lane * 16]);
                int4 c0 = wc[0], c1 = wc[1], c2 = wc[2], c3 = wc[3];
                int cnt[16] = {c0.x,c0.y,c0.z,c0.w, c1.x,c1.y,c1.z,c1.w,
                               c2.x,c2.y,c2.z,c2.w, c3.x,c3.y,c3.z,c3.w};
                int lsum = 0;
#pragma unroll
                for (int j = 0; j < 16; j++) lsum += cnt[j];
                int s = lsum;
#pragma unroll
                for (int d = 1; d < 32; d <<= 1) {
                    int t = __shfl_up_sync(0xFFFFFFFFu, s, d);
                    if (lane >= d) s += t;
                }
                int run = s - lsum;
                const int total = __shfl_sync(0xFFFFFFFFu, s, 31);
                int ov[16];
#pragma unroll
                for (int j = 0; j < 16; j++) { ov[j] = run; run += cnt[j]; }
                int4* wo = reinterpret_cast<int4*>(&g_wcount[ex][lane * 16]);
                wo[0] = make_int4(ov[0],  ov[1],  ov[2],  ov[3]);
                wo[1] = make_int4(ov[4],  ov[5],  ov[6],  ov[7]);
                wo[2] = make_int4(ov[8],  ov[9],  ov[10], ov[11]);
                wo[3] = make_int4(ov[12], ov[13], ov[14], ov[15]);
                if (lane == 0) {
                    g_cnt[ex] = total;
                    out[CNT_OFF + ex] = (float)total;
                }
            }
        }

        pbar();

        // Phase 3: emit inverse map from register-held (e, rk).
        const int slot = e * MAX_TOK + g_wcount[e][chunk] + rk;
        g_src[slot] = a;
        __threadfence();
        __syncthreads();
        if (threadIdx.x == 0) atomicAdd(&g_done, 1u);   // +64 per replay total
        return;
    }

    // ---------------- Slot blocks (bid 64..32831) --------------------------
    const int k = b - PLANNERS;                        // slot id 0..32767
    if (threadIdx.x == 0) {
        // Spread tickets: row k&1023 gets exactly 32 increments per replay.
        const int t = atomicAdd(&g_tick[k & (TICK_ADDRS - 1)][0], 1);
        const unsigned tgt = ((unsigned)(t >> 5) + 1u) * PLANNERS;
        while (*(volatile unsigned*)&g_done < tgt) { }
    }
    __syncthreads();   // orders the reads below after the flag observation

    const int slot = k;
    const int e    = slot >> 10;
    const int si   = slot & (MAX_TOK - 1);
    const int t    = threadIdx.x;
    float4* dst = reinterpret_cast<float4*>(out + (size_t)slot * HIDDEN);
    float4* md  = reinterpret_cast<float4*>(out + META_OFF + (size_t)slot * META_LEN);

    if (si < g_cnt[e]) {
        const int a   = g_src[slot];
        const int c   = a >> 12;
        const int n   = a & (N_PER_CHIP - 1);
        const int tok = n >> 2;
        const float4* src =
            reinterpret_cast<const float4*>(x + ((size_t)c * SEQ + tok) * HIDDEN);
        float4 v0 = src[t];
        float4 v1 = src[t + 256];
        dst[t]       = v0;
        dst[t + 256] = v1;
        if (t == 0) {
            __nv_bfloat16 hb = __float2bfloat16(w[a]);
            unsigned short bits = __bfloat16_as_ushort(hb);
            md[0] = make_float4((float)c, (float)tok, (float)(n & 3), (float)e);
            md[1] = make_float4((float)bits, 0.f, 0.f, 0.f);
        }
    } else {
        const float4 z = make_float4(0.f, 0.f, 0.f, 0.f);
        dst[t]       = z;
        dst[t + 256] = z;
        if (t == 0) {
            const float4 neg = make_float4(-1.f, -1.f, -1.f, -1.f);
            md[0] = neg;
            md[1] = neg;
        }
    }
}

// ---------------------------------------------------------------------------
extern "C" void kernel_launch(void* const* d_in, const int* in_sizes, int n_in,
                              void* d_out, int out_size) {
    const float* x   = (const float*)d_in[0];   // [4,1024,2048] f32
    const float* wts = (const float*)d_in[1];   // [4,1024,4]    f32
    const int*   ind = (const int*)  d_in[2];   // [4,1024,4]    i32
    float* out = (float*)d_out;

    dispatch_kernel<<<PLANNERS + TOTAL_SLOTS, THREADS>>>(x, wts, ind, out);
}